// round 6
// baseline (speedup 1.0000x reference)
#include <cuda_runtime.h>
#include <cuda_bf16.h>
#include <cstdint>
#include <math.h>

// ---------------------------------------------------------------------------
#define MB_ 8192   // batch B
#define HD  768    // hidden H (= K dim)

__device__ __forceinline__ uint32_t smem_to_u32(const void* smem_ptr) {
    uint32_t addr;
    asm("{ .reg .u64 tmp; cvta.to.shared.u64 tmp, %1; cvt.u32.u64 %0, tmp; }"
        : "=r"(addr) : "l"(smem_ptr));
    return addr;
}

// ---------------------------------------------------------------------------
// scratch (device globals; no allocation allowed)
__device__ __nv_bfloat16 g_abf [MB_ * HD];
__device__ __nv_bfloat16 g_w1m [HD * HD];
__device__ __nv_bfloat16 g_w1v [HD * HD];
__device__ __nv_bfloat16 g_w2m [HD * HD];
__device__ __nv_bfloat16 g_w2v [HD * HD];
__device__ __nv_bfloat16 g_t1m [MB_ * HD];
__device__ __nv_bfloat16 g_t1v [MB_ * HD];
__device__ float g_psum  [64 * HD];   // per m-block column sums of mu
__device__ float g_psq   [64 * HD];   // per m-block column sums of mu^2
__device__ float g_siv   [64 * HD];   // per m-block column sums of iv
__device__ float g_smuiv [64 * HD];   // per m-block column sums of mu*iv
__device__ float g_ppos  [384];       // per-CTA sum (mu-b)^2*iv
__device__ float g_pm2   [384];       // per-CTA sum mu^2*iv
__device__ float g_negp  [24];        // per-fc-block negative partials
__device__ int   g_cnt;               // completion counter (self-resetting)

// ---------------------------------------------------------------------------
// all fp32->bf16 conversions in one launch
__global__ void cvt_all(const float* __restrict__ A,
                        const float* __restrict__ W1m, const float* __restrict__ W1v,
                        const float* __restrict__ W2m, const float* __restrict__ W2v)
{
    int b = blockIdx.x;
    const float* src; __nv_bfloat16* dst; size_t base;
    if (b < 6144) { src = A; dst = g_abf; base = (size_t)b * 1024; }
    else {
        int r = b - 6144, w = r / 576, rb = r % 576;
        base = (size_t)rb * 1024;
        if      (w == 0) { src = W1m; dst = g_w1m; }
        else if (w == 1) { src = W1v; dst = g_w1v; }
        else if (w == 2) { src = W2m; dst = g_w2m; }
        else             { src = W2v; dst = g_w2v; }
    }
    size_t i = base + (size_t)threadIdx.x * 4;
    float4 v = *(const float4*)(src + i);
    __nv_bfloat162 lo = __floats2bfloat162_rn(v.x, v.y);
    __nv_bfloat162 hi = __floats2bfloat162_rn(v.z, v.w);
    *(uint2*)(dst + i) = make_uint2(*(uint32_t*)&lo, *(uint32_t*)&hi);
}

// ---------------------------------------------------------------------------
// HMMA primitives
__device__ __forceinline__ void ldsm_x4(uint32_t* r, uint32_t addr) {
    asm volatile("ldmatrix.sync.aligned.m8n8.x4.shared.b16 {%0,%1,%2,%3}, [%4];"
                 : "=r"(r[0]), "=r"(r[1]), "=r"(r[2]), "=r"(r[3]) : "r"(addr));
}
__device__ __forceinline__ void mma_bf16(float* c, const uint32_t* a, const uint32_t* b) {
    asm volatile(
        "mma.sync.aligned.m16n8k16.row.col.f32.bf16.bf16.f32 "
        "{%0,%1,%2,%3}, {%4,%5,%6,%7}, {%8,%9}, {%0,%1,%2,%3};"
        : "+f"(c[0]), "+f"(c[1]), "+f"(c[2]), "+f"(c[3])
        : "r"(a[0]), "r"(a[1]), "r"(a[2]), "r"(a[3]), "r"(b[0]), "r"(b[1]));
}
#define CP_ASYNC16(dst, src) \
    asm volatile("cp.async.cg.shared.global [%0], [%1], 16;" :: "r"(dst), "l"(src))
#define CP_COMMIT() asm volatile("cp.async.commit_group;" ::: "memory")
#define CP_WAIT1()  asm volatile("cp.async.wait_group 1;" ::: "memory")

// ---------------------------------------------------------------------------
// shared 3-stage single-sync mainloop (CTA 128x128, BK=64, 8 warps of 64x32)
// smem: 3 stages x (16KB A + 16KB W) = 96KB starting at sb
__device__ __forceinline__ void mainloop_3s(
    uint32_t sb, const __nv_bfloat16* __restrict__ Ag,
    const __nv_bfloat16* __restrict__ Wg,
    int tid, int lane, int wm0, int wn0, float acc[4][4][4])
{
    const int lrow = tid >> 3;
    const int lcg  = tid & 7;
    auto load_tiles = [&](int c, int stage) {
        const uint32_t ab = sb + stage * 32768;
        const uint32_t wb = ab + 16384;
        const int k0 = c * 64;
#pragma unroll
        for (int r = 0; r < 4; r++) {
            int row = r * 32 + lrow;
            uint32_t off = ((uint32_t)row << 7) + ((uint32_t)(lcg ^ (row & 7)) << 4);
            CP_ASYNC16(ab + off, Ag + (size_t)row * HD + k0 + lcg * 8);
            CP_ASYNC16(wb + off, Wg + (size_t)row * HD + k0 + lcg * 8);
        }
    };

    load_tiles(0, 0); CP_COMMIT();
    load_tiles(1, 1); CP_COMMIT();

    const int arow = lane & 15;
    const int ahi  = lane >> 4;
    const int bl8  = lane & 7;
    const int bsel = lane >> 3;

    for (int c = 0; c < 12; c++) {
        CP_WAIT1();
        __syncthreads();
        const uint32_t ab = sb + (c % 3) * 32768;
        const uint32_t wb = ab + 16384;
#pragma unroll
        for (int ks = 0; ks < 4; ks++) {
            uint32_t afr[4][4];
#pragma unroll
            for (int mf = 0; mf < 4; mf++) {
                int row = wm0 + mf * 16 + arow;
                uint32_t addr = ab + ((uint32_t)row << 7)
                              + ((uint32_t)((2 * ks + ahi) ^ (row & 7)) << 4);
                ldsm_x4(afr[mf], addr);
            }
            uint32_t bfr[2][4];
#pragma unroll
            for (int nfp = 0; nfp < 2; nfp++) {
                int row = wn0 + nfp * 16 + ((bsel >> 1) << 3) + bl8;
                uint32_t addr = wb + ((uint32_t)row << 7)
                              + ((uint32_t)((2 * ks + (bsel & 1)) ^ (row & 7)) << 4);
                ldsm_x4(bfr[nfp], addr);
            }
#pragma unroll
            for (int nf = 0; nf < 4; nf++) {
                const uint32_t* bp = &bfr[nf >> 1][(nf & 1) * 2];
#pragma unroll
                for (int mf = 0; mf < 4; mf++)
                    mma_bf16(acc[mf][nf], afr[mf], bp);
            }
        }
        // refill buffer (c+2)%3 == buffer drained at iter c-1 (3 stages -> safe)
        if (c + 2 < 12) load_tiles(c + 2, (c + 2) % 3);
        CP_COMMIT();
    }
}

// ---------------------------------------------------------------------------
// GEMM1+2: C = tanh(A@W^T + b) -> bf16, gridDim.z selects weight/bias/out set
#define GT_SMEM 98304

__global__ void __launch_bounds__(256, 2)
gemm_tanh(const __nv_bfloat16* __restrict__ A,
          const __nv_bfloat16* __restrict__ W0,
          const __nv_bfloat16* __restrict__ W1,
          const float* __restrict__ bias0,
          const float* __restrict__ bias1,
          __nv_bfloat16* __restrict__ out0,
          __nv_bfloat16* __restrict__ out1)
{
    extern __shared__ char smem[];
    const uint32_t sb = smem_to_u32(smem);
    const int tid  = threadIdx.x;
    const int lane = tid & 31;
    const int wid  = tid >> 5;
    const int wm0  = (wid >> 2) * 64;
    const int wn0  = (wid & 3) * 32;
    const int bm   = blockIdx.y * 128;
    const int bn   = blockIdx.x * 128;

    const __nv_bfloat16* W = blockIdx.z ? W1 : W0;
    const float* bias      = blockIdx.z ? bias1 : bias0;
    __nv_bfloat16* C       = blockIdx.z ? out1 : out0;

    float acc[4][4][4];
#pragma unroll
    for (int i = 0; i < 4; i++)
#pragma unroll
        for (int j = 0; j < 4; j++)
#pragma unroll
            for (int q = 0; q < 4; q++) acc[i][j][q] = 0.f;

    mainloop_3s(sb, A + (size_t)bm * HD, W + (size_t)bn * HD,
                tid, lane, wm0, wn0, acc);

    const int g  = lane >> 2;
    const int tq = lane & 3;
#pragma unroll
    for (int mf = 0; mf < 4; mf++) {
#pragma unroll
        for (int nf = 0; nf < 4; nf++) {
            const int m0 = bm + wm0 + mf * 16 + g;
            const int n  = bn + wn0 + nf * 8 + tq * 2;
            const float bv0 = __ldg(&bias[n]);
            const float bv1 = __ldg(&bias[n + 1]);
            __nv_bfloat162 p0 = __floats2bfloat162_rn(
                tanhf(acc[mf][nf][0] + bv0), tanhf(acc[mf][nf][1] + bv1));
            __nv_bfloat162 p1 = __floats2bfloat162_rn(
                tanhf(acc[mf][nf][2] + bv0), tanhf(acc[mf][nf][3] + bv1));
            *(__nv_bfloat162*)&C[(size_t)m0 * HD + n]       = p0;
            *(__nv_bfloat162*)&C[(size_t)(m0 + 8) * HD + n] = p1;
        }
    }
}

// ---------------------------------------------------------------------------
// Fused GEMM3+GEMM4: loop1 computes mu tile (kept in 32 packed bf16x2 REGS),
// emits column S_mu/S_mu2 partials; loop2 computes iv in regs and emits
// P, M2 scalars + S_iv/S_muiv column partials. 3-stage pipeline both loops.
#define FU_STG    98304
#define FU_SMEM   (98304 + 2176)

__global__ void __launch_bounds__(256, 2)
gemm_fused34(const __nv_bfloat16* __restrict__ A1,   // t1m
             const __nv_bfloat16* __restrict__ Wm,   // w2m
             const float* __restrict__ bm_,
             const __nv_bfloat16* __restrict__ A2,   // t1v
             const __nv_bfloat16* __restrict__ Wv,   // w2v
             const float* __restrict__ bv_,
             const float* __restrict__ mbin)
{
    extern __shared__ char smem[];
    const uint32_t sb = smem_to_u32(smem);
    const int tid  = threadIdx.x;
    const int lane = tid & 31;
    const int wid  = tid >> 5;
    const int wm0  = (wid >> 2) * 64;
    const int wn0  = (wid & 3) * 32;
    const int bm   = blockIdx.y * 128;
    const int bn   = blockIdx.x * 128;
    const int g    = lane >> 2;
    const int tq   = lane & 3;
    const int mwarp = wid >> 2;

    float acc[4][4][4];
#pragma unroll
    for (int i = 0; i < 4; i++)
#pragma unroll
        for (int j = 0; j < 4; j++)
#pragma unroll
            for (int q = 0; q < 4; q++) acc[i][j][q] = 0.f;

    // ---- loop 1: mu ----
    mainloop_3s(sb, A1 + (size_t)bm * HD, Wm + (size_t)bn * HD,
                tid, lane, wm0, wn0, acc);

    // ---- epilogue 1: mu -> packed regs + column S_mu / S_mu2 partials ----
    uint32_t mu_pk[4][4][2];
    {
        float cs[4][2], cq[4][2];
#pragma unroll
        for (int nf = 0; nf < 4; nf++) { cs[nf][0]=cs[nf][1]=cq[nf][0]=cq[nf][1]=0.f; }
#pragma unroll
        for (int mf = 0; mf < 4; mf++) {
#pragma unroll
            for (int nf = 0; nf < 4; nf++) {
                const int n  = bn + wn0 + nf * 8 + tq * 2;
                const float bv0 = __ldg(&bm_[n]);
                const float bv1 = __ldg(&bm_[n + 1]);
                float v00 = acc[mf][nf][0] + bv0;
                float v01 = acc[mf][nf][1] + bv1;
                float v10 = acc[mf][nf][2] + bv0;
                float v11 = acc[mf][nf][3] + bv1;
                __nv_bfloat162 p0 = __floats2bfloat162_rn(v00, v01);
                __nv_bfloat162 p1 = __floats2bfloat162_rn(v10, v11);
                mu_pk[mf][nf][0] = *(uint32_t*)&p0;
                mu_pk[mf][nf][1] = *(uint32_t*)&p1;
                cs[nf][0] += v00 + v10;  cq[nf][0] += v00*v00 + v10*v10;
                cs[nf][1] += v01 + v11;  cq[nf][1] += v01*v01 + v11*v11;
            }
        }
#pragma unroll
        for (int msk = 4; msk <= 16; msk <<= 1)
#pragma unroll
            for (int nf = 0; nf < 4; nf++)
#pragma unroll
                for (int j = 0; j < 2; j++) {
                    cs[nf][j] += __shfl_xor_sync(0xffffffff, cs[nf][j], msk);
                    cq[nf][j] += __shfl_xor_sync(0xffffffff, cq[nf][j], msk);
                }
        float* sred = (float*)(smem + FU_STG);   // [mwarp][2][128]
        if (lane < 4) {
#pragma unroll
            for (int nf = 0; nf < 4; nf++)
#pragma unroll
                for (int j = 0; j < 2; j++) {
                    int col = wn0 + nf * 8 + lane * 2 + j;
                    sred[(mwarp * 2 + 0) * 128 + col] = cs[nf][j];
                    sred[(mwarp * 2 + 1) * 128 + col] = cq[nf][j];
                }
        }
        __syncthreads();
        if (tid < 128) {
            g_psum[blockIdx.y * HD + bn + tid] = sred[0 * 128 + tid] + sred[2 * 128 + tid];
            g_psq [blockIdx.y * HD + bn + tid] = sred[1 * 128 + tid] + sred[3 * 128 + tid];
        }
    }

    // ---- loop 2: iv pre-activation ----
#pragma unroll
    for (int i = 0; i < 4; i++)
#pragma unroll
        for (int j = 0; j < 4; j++)
#pragma unroll
            for (int q = 0; q < 4; q++) acc[i][j][q] = 0.f;

    mainloop_3s(sb, A2 + (size_t)bm * HD, Wv + (size_t)bn * HD,
                tid, lane, wm0, wn0, acc);

    // ---- epilogue 2: P, M2 scalars + S_iv / S_muiv column partials ----
    {
        float p = 0.f, m2 = 0.f;
        float ci[4][2], cm[4][2];
#pragma unroll
        for (int nf = 0; nf < 4; nf++) { ci[nf][0]=ci[nf][1]=cm[nf][0]=cm[nf][1]=0.f; }
#pragma unroll
        for (int mf = 0; mf < 4; mf++) {
#pragma unroll
            for (int nf = 0; nf < 4; nf++) {
                const int m0 = bm + wm0 + mf * 16 + g;
                const int n  = bn + wn0 + nf * 8 + tq * 2;
                const float bv0 = __ldg(&bv_[n]);
                const float bv1 = __ldg(&bv_[n + 1]);
                float iv00 = __expf(-tanhf(acc[mf][nf][0] + bv0));
                float iv01 = __expf(-tanhf(acc[mf][nf][1] + bv1));
                float iv10 = __expf(-tanhf(acc[mf][nf][2] + bv0));
                float iv11 = __expf(-tanhf(acc[mf][nf][3] + bv1));
                __nv_bfloat162 q0 = *(__nv_bfloat162*)&mu_pk[mf][nf][0];
                __nv_bfloat162 q1 = *(__nv_bfloat162*)&mu_pk[mf][nf][1];
                float mu00 = __bfloat162float(q0.x), mu01 = __bfloat162float(q0.y);
                float mu10 = __bfloat162float(q1.x), mu11 = __bfloat162float(q1.y);
                float2 mb0 = *(const float2*)&mbin[(size_t)m0 * HD + n];
                float2 mb1 = *(const float2*)&mbin[(size_t)(m0 + 8) * HD + n];
                float d;
                d = mu00 - mb0.x; p += d * d * iv00;
                d = mu01 - mb0.y; p += d * d * iv01;
                d = mu10 - mb1.x; p += d * d * iv10;
                d = mu11 - mb1.y; p += d * d * iv11;
                m2 += mu00*mu00*iv00 + mu01*mu01*iv01 + mu10*mu10*iv10 + mu11*mu11*iv11;
                ci[nf][0] += iv00 + iv10;           ci[nf][1] += iv01 + iv11;
                cm[nf][0] += mu00*iv00 + mu10*iv10; cm[nf][1] += mu01*iv01 + mu11*iv11;
            }
        }
#pragma unroll
        for (int msk = 4; msk <= 16; msk <<= 1)
#pragma unroll
            for (int nf = 0; nf < 4; nf++)
#pragma unroll
                for (int j = 0; j < 2; j++) {
                    ci[nf][j] += __shfl_xor_sync(0xffffffff, ci[nf][j], msk);
                    cm[nf][j] += __shfl_xor_sync(0xffffffff, cm[nf][j], msk);
                }
#pragma unroll
        for (int msk = 16; msk >= 1; msk >>= 1) {
            p  += __shfl_xor_sync(0xffffffff, p,  msk);
            m2 += __shfl_xor_sync(0xffffffff, m2, msk);
        }
        float* sred = (float*)(smem + FU_STG);
        float* ssc  = sred + 512;
        if (lane < 4) {
#pragma unroll
            for (int nf = 0; nf < 4; nf++)
#pragma unroll
                for (int j = 0; j < 2; j++) {
                    int col = wn0 + nf * 8 + lane * 2 + j;
                    sred[(mwarp * 2 + 0) * 128 + col] = ci[nf][j];
                    sred[(mwarp * 2 + 1) * 128 + col] = cm[nf][j];
                }
        }
        if (lane == 0) { ssc[wid] = p; ssc[8 + wid] = m2; }
        __syncthreads();
        if (tid < 128) {
            g_siv  [blockIdx.y * HD + bn + tid] = sred[0 * 128 + tid] + sred[2 * 128 + tid];
            g_smuiv[blockIdx.y * HD + bn + tid] = sred[1 * 128 + tid] + sred[3 * 128 + tid];
        }
        if (tid == 0) {
            float P = 0.f, M2 = 0.f;
#pragma unroll
            for (int w = 0; w < 8; w++) { P += ssc[w]; M2 += ssc[8 + w]; }
            int bid = blockIdx.y * gridDim.x + blockIdx.x;
            g_ppos[bid] = P;
            g_pm2 [bid] = M2;
        }
    }
}

// ---------------------------------------------------------------------------
// fc_final: coalesced column reduce + negative term; last block finishes scalars.
// grid 24 x 256: warp = slab-group (8 slabs), lane = column (32 cols/block).
__global__ void fc_final(float* __restrict__ out)
{
    const int tid  = threadIdx.x;
    const int lane = tid & 31;
    const int w    = tid >> 5;            // 0..7
    const int h    = blockIdx.x * 32 + lane;

    float smu = 0.f, sm2 = 0.f, siv = 0.f, smv = 0.f;
#pragma unroll
    for (int s = 0; s < 8; s++) {
        int idx = (w * 8 + s) * HD + h;   // coalesced across lanes
        smu += g_psum[idx]; sm2 += g_psq[idx];
        siv += g_siv[idx];  smv += g_smuiv[idx];
    }
    __shared__ float red[4][8][32];
    red[0][w][lane] = smu; red[1][w][lane] = sm2;
    red[2][w][lane] = siv; red[3][w][lane] = smv;
    __syncthreads();
    if (w == 0) {
        float a = 0.f, b = 0.f, c = 0.f, d = 0.f;
#pragma unroll
        for (int k = 0; k < 8; k++) {
            a += red[0][k][lane]; b += red[1][k][lane];
            c += red[2][k][lane]; d += red[3][k][lane];
        }
        float neg = (b * (1.0f / MB_)) * c - 2.0f * (a * (1.0f / MB_)) * d;
#pragma unroll
        for (int msk = 16; msk >= 1; msk >>= 1)
            neg += __shfl_xor_sync(0xffffffff, neg, msk);
        if (lane == 0) g_negp[blockIdx.x] = neg;
    }

    // last-block finishes the scalar reduction
    __shared__ int is_last;
    __threadfence();
    if (tid == 0) {
        int prev = atomicAdd(&g_cnt, 1);
        is_last = (prev == 23);
    }
    __syncthreads();
    if (is_last) {
        __threadfence();
        float p = 0.f, m2 = 0.f, ng = 0.f;
        for (int i = tid; i < 384; i += 256) { p += g_ppos[i]; m2 += g_pm2[i]; }
        if (tid < 24) ng = g_negp[tid];
        __shared__ float sp[256], sm[256], sg[256];
        sp[tid] = p; sm[tid] = m2; sg[tid] = ng;
        __syncthreads();
        for (int s = 128; s > 0; s >>= 1) {
            if (tid < s) { sp[tid] += sp[tid+s]; sm[tid] += sm[tid+s]; sg[tid] += sg[tid+s]; }
            __syncthreads();
        }
        if (tid == 0) {
            float P = sp[0];
            float N = sg[0] + sm[0];
            out[0] = -0.5f * P / (float)MB_;
            out[1] = 0.5f * (N - P) / (float)MB_;
            g_cnt = 0;                    // reset for next replay
        }
    }
}

// ---------------------------------------------------------------------------
extern "C" void kernel_launch(void* const* d_in, const int* in_sizes, int n_in,
                              void* d_out, int out_size)
{
    const float* A   = (const float*)d_in[0];
    const float* Mb  = (const float*)d_in[1];
    const float* W1m = (const float*)d_in[2];
    const float* b1m = (const float*)d_in[3];
    const float* W2m = (const float*)d_in[4];
    const float* b2m = (const float*)d_in[5];
    const float* W1v = (const float*)d_in[6];
    const float* b1v = (const float*)d_in[7];
    const float* W2v = (const float*)d_in[8];
    const float* b2v = (const float*)d_in[9];

    __nv_bfloat16 *abf, *w1m, *w1v, *w2m, *w2v, *t1m, *t1v;
    cudaGetSymbolAddress((void**)&abf, g_abf);
    cudaGetSymbolAddress((void**)&w1m, g_w1m);
    cudaGetSymbolAddress((void**)&w1v, g_w1v);
    cudaGetSymbolAddress((void**)&w2m, g_w2m);
    cudaGetSymbolAddress((void**)&w2v, g_w2v);
    cudaGetSymbolAddress((void**)&t1m, g_t1m);
    cudaGetSymbolAddress((void**)&t1v, g_t1v);

    cudaFuncSetAttribute(gemm_tanh,    cudaFuncAttributeMaxDynamicSharedMemorySize, GT_SMEM);
    cudaFuncSetAttribute(gemm_fused34, cudaFuncAttributeMaxDynamicSharedMemorySize, FU_SMEM);

    cvt_all<<<6144 + 4 * 576, 256>>>(A, W1m, W1v, W2m, W2v);

    dim3 grid12(HD / 128, MB_ / 128, 2);  // (6, 64, 2)
    gemm_tanh<<<grid12, 256, GT_SMEM>>>(abf, w1m, w1v, b1m, b1v, t1m, t1v);

    dim3 grid(HD / 128, MB_ / 128);       // (6, 64)
    gemm_fused34<<<grid, 256, FU_SMEM>>>(t1m, w2m, b2m, t1v, w2v, b2v, Mb);

    fc_final<<<24, 256>>>((float*)d_out);
}

// round 7
// speedup vs baseline: 1.0544x; 1.0544x over previous
#include <cuda_runtime.h>
#include <cuda_bf16.h>
#include <cstdint>
#include <math.h>

// ---------------------------------------------------------------------------
#define MB_ 8192   // batch B
#define HD  768    // hidden H (= K dim)

__device__ __forceinline__ uint32_t smem_to_u32(const void* smem_ptr) {
    uint32_t addr;
    asm("{ .reg .u64 tmp; cvta.to.shared.u64 tmp, %1; cvt.u32.u64 %0, tmp; }"
        : "=r"(addr) : "l"(smem_ptr));
    return addr;
}

// ---------------------------------------------------------------------------
// scratch (device globals; no allocation allowed)
__device__ __nv_bfloat16 g_abf [MB_ * HD];
__device__ __nv_bfloat16 g_w1m [HD * HD];
__device__ __nv_bfloat16 g_w1v [HD * HD];
__device__ __nv_bfloat16 g_w2m [HD * HD];
__device__ __nv_bfloat16 g_w2v [HD * HD];
__device__ __nv_bfloat16 g_t1m [MB_ * HD];
__device__ __nv_bfloat16 g_t1v [MB_ * HD];
__device__ float g_psum  [64 * HD];   // per m-block column sums of mu
__device__ float g_psq   [64 * HD];   // per m-block column sums of mu^2
__device__ float g_siv   [64 * HD];   // per m-block column sums of iv
__device__ float g_smuiv [64 * HD];   // per m-block column sums of mu*iv
__device__ float g_ppos  [384];       // per-CTA sum (mu-b)^2*iv
__device__ float g_pm2   [384];       // per-CTA sum mu^2*iv
__device__ float g_negp  [24];        // per-fc1-block negative partials

// ---------------------------------------------------------------------------
// all fp32->bf16 conversions in one launch
__global__ void cvt_all(const float* __restrict__ A,
                        const float* __restrict__ W1m, const float* __restrict__ W1v,
                        const float* __restrict__ W2m, const float* __restrict__ W2v)
{
    int b = blockIdx.x;
    const float* src; __nv_bfloat16* dst; size_t base;
    if (b < 6144) { src = A; dst = g_abf; base = (size_t)b * 1024; }
    else {
        int r = b - 6144, w = r / 576, rb = r % 576;
        base = (size_t)rb * 1024;
        if      (w == 0) { src = W1m; dst = g_w1m; }
        else if (w == 1) { src = W1v; dst = g_w1v; }
        else if (w == 2) { src = W2m; dst = g_w2m; }
        else             { src = W2v; dst = g_w2v; }
    }
    size_t i = base + (size_t)threadIdx.x * 4;
    float4 v = *(const float4*)(src + i);
    __nv_bfloat162 lo = __floats2bfloat162_rn(v.x, v.y);
    __nv_bfloat162 hi = __floats2bfloat162_rn(v.z, v.w);
    *(uint2*)(dst + i) = make_uint2(*(uint32_t*)&lo, *(uint32_t*)&hi);
}

// ---------------------------------------------------------------------------
// HMMA primitives
__device__ __forceinline__ void ldsm_x4(uint32_t* r, uint32_t addr) {
    asm volatile("ldmatrix.sync.aligned.m8n8.x4.shared.b16 {%0,%1,%2,%3}, [%4];"
                 : "=r"(r[0]), "=r"(r[1]), "=r"(r[2]), "=r"(r[3]) : "r"(addr));
}
__device__ __forceinline__ void mma_bf16(float* c, const uint32_t* a, const uint32_t* b) {
    asm volatile(
        "mma.sync.aligned.m16n8k16.row.col.f32.bf16.bf16.f32 "
        "{%0,%1,%2,%3}, {%4,%5,%6,%7}, {%8,%9}, {%0,%1,%2,%3};"
        : "+f"(c[0]), "+f"(c[1]), "+f"(c[2]), "+f"(c[3])
        : "r"(a[0]), "r"(a[1]), "r"(a[2]), "r"(a[3]), "r"(b[0]), "r"(b[1]));
}
#define CP_ASYNC16(dst, src) \
    asm volatile("cp.async.cg.shared.global [%0], [%1], 16;" :: "r"(dst), "l"(src))
#define CP_COMMIT() asm volatile("cp.async.commit_group;" ::: "memory")
#define CP_WAIT1()  asm volatile("cp.async.wait_group 1;" ::: "memory")

// ---------------------------------------------------------------------------
// GEMM1+2: C = tanh(A@W^T + b) -> bf16, gridDim.z selects (W1m,b1m,t1m)/(W1v,b1v,t1v)
// CTA 128x128, BK=64, 3-stage cp.async, 8 warps of 64x32.
#define GT_SMEM 98304

__global__ void __launch_bounds__(256, 2)
gemm_tanh(const __nv_bfloat16* __restrict__ A,
          const __nv_bfloat16* __restrict__ W0,
          const __nv_bfloat16* __restrict__ W1,
          const float* __restrict__ bias0,
          const float* __restrict__ bias1,
          __nv_bfloat16* __restrict__ out0,
          __nv_bfloat16* __restrict__ out1)
{
    extern __shared__ char smem[];
    const uint32_t sb = smem_to_u32(smem);
    const int tid  = threadIdx.x;
    const int lane = tid & 31;
    const int wid  = tid >> 5;
    const int wm0  = (wid >> 2) * 64;
    const int wn0  = (wid & 3) * 32;
    const int bm   = blockIdx.y * 128;
    const int bn   = blockIdx.x * 128;

    const __nv_bfloat16* W = blockIdx.z ? W1 : W0;
    const float* bias      = blockIdx.z ? bias1 : bias0;
    __nv_bfloat16* C       = blockIdx.z ? out1 : out0;

    float acc[4][4][4];
#pragma unroll
    for (int i = 0; i < 4; i++)
#pragma unroll
        for (int j = 0; j < 4; j++)
#pragma unroll
            for (int q = 0; q < 4; q++) acc[i][j][q] = 0.f;

    const __nv_bfloat16* Ag = A + (size_t)bm * HD;
    const __nv_bfloat16* Wg = W + (size_t)bn * HD;

    const int lrow = tid >> 3;
    const int lcg  = tid & 7;
    auto load_tiles = [&](int c, int stage) {
        const uint32_t ab = sb + stage * 32768;
        const uint32_t wb = ab + 16384;
        const int k0 = c * 64;
#pragma unroll
        for (int r = 0; r < 4; r++) {
            int row = r * 32 + lrow;
            uint32_t off = ((uint32_t)row << 7) + ((uint32_t)(lcg ^ (row & 7)) << 4);
            CP_ASYNC16(ab + off, Ag + (size_t)row * HD + k0 + lcg * 8);
            CP_ASYNC16(wb + off, Wg + (size_t)row * HD + k0 + lcg * 8);
        }
    };

    load_tiles(0, 0); CP_COMMIT();
    load_tiles(1, 1); CP_COMMIT();

    const int arow = lane & 15;
    const int ahi  = lane >> 4;
    const int bl8  = lane & 7;
    const int bsel = lane >> 3;

    for (int c = 0; c < 12; c++) {
        CP_WAIT1();
        __syncthreads();
        if (c + 2 < 12) load_tiles(c + 2, (c + 2) % 3);
        CP_COMMIT();

        const uint32_t ab = sb + (c % 3) * 32768;
        const uint32_t wb = ab + 16384;
#pragma unroll
        for (int ks = 0; ks < 4; ks++) {
            uint32_t afr[4][4];
#pragma unroll
            for (int mf = 0; mf < 4; mf++) {
                int row = wm0 + mf * 16 + arow;
                uint32_t addr = ab + ((uint32_t)row << 7)
                              + ((uint32_t)((2 * ks + ahi) ^ (row & 7)) << 4);
                ldsm_x4(afr[mf], addr);
            }
            uint32_t bfr[2][4];
#pragma unroll
            for (int nfp = 0; nfp < 2; nfp++) {
                int row = wn0 + nfp * 16 + ((bsel >> 1) << 3) + bl8;
                uint32_t addr = wb + ((uint32_t)row << 7)
                              + ((uint32_t)((2 * ks + (bsel & 1)) ^ (row & 7)) << 4);
                ldsm_x4(bfr[nfp], addr);
            }
#pragma unroll
            for (int nf = 0; nf < 4; nf++) {
                const uint32_t* bp = &bfr[nf >> 1][(nf & 1) * 2];
#pragma unroll
                for (int mf = 0; mf < 4; mf++)
                    mma_bf16(acc[mf][nf], afr[mf], bp);
            }
        }
        __syncthreads();
    }

    const int g  = lane >> 2;
    const int tq = lane & 3;
#pragma unroll
    for (int mf = 0; mf < 4; mf++) {
#pragma unroll
        for (int nf = 0; nf < 4; nf++) {
            const int m0 = bm + wm0 + mf * 16 + g;
            const int n  = bn + wn0 + nf * 8 + tq * 2;
            const float bv0 = __ldg(&bias[n]);
            const float bv1 = __ldg(&bias[n + 1]);
            __nv_bfloat162 p0 = __floats2bfloat162_rn(
                tanhf(acc[mf][nf][0] + bv0), tanhf(acc[mf][nf][1] + bv1));
            __nv_bfloat162 p1 = __floats2bfloat162_rn(
                tanhf(acc[mf][nf][2] + bv0), tanhf(acc[mf][nf][3] + bv1));
            *(__nv_bfloat162*)&C[(size_t)m0 * HD + n]       = p0;
            *(__nv_bfloat162*)&C[(size_t)(m0 + 8) * HD + n] = p1;
        }
    }
}

// ---------------------------------------------------------------------------
// Fused GEMM3+GEMM4 (R5 structure: mu tile in smem bf16, 2-stage pipeline)
#define FU_PIPE   65536
#define FU_MU     65536              // mu tile offset
#define FU_MUSTR  264                // padded row stride (bytes)
#define FU_STG    (65536 + 33792)    // staging offset
#define FU_SMEM   (65536 + 33792 + 2176)

__device__ __forceinline__ void fused_mainloop(
    uint32_t sb, const __nv_bfloat16* __restrict__ Ag,
    const __nv_bfloat16* __restrict__ Wg,
    int tid, int lane, int wm0, int wn0, float acc[4][4][4])
{
    const int lrow = tid >> 3;
    const int lcg  = tid & 7;
    auto load_tiles = [&](int c, int stage) {
        const uint32_t ab = sb + stage * 32768;
        const uint32_t wb = ab + 16384;
        const int k0 = c * 64;
#pragma unroll
        for (int r = 0; r < 4; r++) {
            int row = r * 32 + lrow;
            uint32_t off = ((uint32_t)row << 7) + ((uint32_t)(lcg ^ (row & 7)) << 4);
            CP_ASYNC16(ab + off, Ag + (size_t)row * HD + k0 + lcg * 8);
            CP_ASYNC16(wb + off, Wg + (size_t)row * HD + k0 + lcg * 8);
        }
    };

    load_tiles(0, 0); CP_COMMIT();
    load_tiles(1, 1); CP_COMMIT();

    const int arow = lane & 15;
    const int ahi  = lane >> 4;
    const int bl8  = lane & 7;
    const int bsel = lane >> 3;

    for (int c = 0; c < 12; c++) {
        CP_WAIT1();                      // chunk c resident
        __syncthreads();
        const uint32_t ab = sb + (c & 1) * 32768;
        const uint32_t wb = ab + 16384;
#pragma unroll
        for (int ks = 0; ks < 4; ks++) {
            uint32_t afr[4][4];
#pragma unroll
            for (int mf = 0; mf < 4; mf++) {
                int row = wm0 + mf * 16 + arow;
                uint32_t addr = ab + ((uint32_t)row << 7)
                              + ((uint32_t)((2 * ks + ahi) ^ (row & 7)) << 4);
                ldsm_x4(afr[mf], addr);
            }
            uint32_t bfr[2][4];
#pragma unroll
            for (int nfp = 0; nfp < 2; nfp++) {
                int row = wn0 + nfp * 16 + ((bsel >> 1) << 3) + bl8;
                uint32_t addr = wb + ((uint32_t)row << 7)
                              + ((uint32_t)((2 * ks + (bsel & 1)) ^ (row & 7)) << 4);
                ldsm_x4(bfr[nfp], addr);
            }
#pragma unroll
            for (int nf = 0; nf < 4; nf++) {
                const uint32_t* bp = &bfr[nf >> 1][(nf & 1) * 2];
#pragma unroll
                for (int mf = 0; mf < 4; mf++)
                    mma_bf16(acc[mf][nf], afr[mf], bp);
            }
        }
        __syncthreads();                 // all warps done with stage c&1
        if (c + 2 < 12) load_tiles(c + 2, c & 1);
        CP_COMMIT();                     // keep group-count invariant
    }
}

__global__ void __launch_bounds__(256, 2)
gemm_fused34(const __nv_bfloat16* __restrict__ A1,   // t1m
             const __nv_bfloat16* __restrict__ Wm,   // w2m
             const float* __restrict__ bm_,
             const __nv_bfloat16* __restrict__ A2,   // t1v
             const __nv_bfloat16* __restrict__ Wv,   // w2v
             const float* __restrict__ bv_,
             const float* __restrict__ mbin)
{
    extern __shared__ char smem[];
    const uint32_t sb = smem_to_u32(smem);
    const int tid  = threadIdx.x;
    const int lane = tid & 31;
    const int wid  = tid >> 5;
    const int wm0  = (wid >> 2) * 64;
    const int wn0  = (wid & 3) * 32;
    const int bm   = blockIdx.y * 128;
    const int bn   = blockIdx.x * 128;
    const int g    = lane >> 2;
    const int tq   = lane & 3;
    const int mwarp = wid >> 2;

    float acc[4][4][4];
#pragma unroll
    for (int i = 0; i < 4; i++)
#pragma unroll
        for (int j = 0; j < 4; j++)
#pragma unroll
            for (int q = 0; q < 4; q++) acc[i][j][q] = 0.f;

    // ---- loop 1: mu ----
    fused_mainloop(sb, A1 + (size_t)bm * HD, Wm + (size_t)bn * HD,
                   tid, lane, wm0, wn0, acc);

    // ---- epilogue 1: mu -> smem bf16 + column S_mu / S_mu2 partials ----
    {
        float cs[4][2], cq[4][2];
#pragma unroll
        for (int nf = 0; nf < 4; nf++) { cs[nf][0]=cs[nf][1]=cq[nf][0]=cq[nf][1]=0.f; }
#pragma unroll
        for (int mf = 0; mf < 4; mf++) {
#pragma unroll
            for (int nf = 0; nf < 4; nf++) {
                const int ml = wm0 + mf * 16 + g;
                const int n  = bn + wn0 + nf * 8 + tq * 2;
                const int nl = wn0 + nf * 8 + tq * 2;
                const float bv0 = __ldg(&bm_[n]);
                const float bv1 = __ldg(&bm_[n + 1]);
                float v00 = acc[mf][nf][0] + bv0;
                float v01 = acc[mf][nf][1] + bv1;
                float v10 = acc[mf][nf][2] + bv0;
                float v11 = acc[mf][nf][3] + bv1;
                __nv_bfloat162 p0 = __floats2bfloat162_rn(v00, v01);
                __nv_bfloat162 p1 = __floats2bfloat162_rn(v10, v11);
                *(__nv_bfloat162*)(smem + FU_MU + ml * FU_MUSTR + nl * 2)       = p0;
                *(__nv_bfloat162*)(smem + FU_MU + (ml + 8) * FU_MUSTR + nl * 2) = p1;
                cs[nf][0] += v00 + v10;  cq[nf][0] += v00*v00 + v10*v10;
                cs[nf][1] += v01 + v11;  cq[nf][1] += v01*v01 + v11*v11;
            }
        }
#pragma unroll
        for (int msk = 4; msk <= 16; msk <<= 1)
#pragma unroll
            for (int nf = 0; nf < 4; nf++)
#pragma unroll
                for (int j = 0; j < 2; j++) {
                    cs[nf][j] += __shfl_xor_sync(0xffffffff, cs[nf][j], msk);
                    cq[nf][j] += __shfl_xor_sync(0xffffffff, cq[nf][j], msk);
                }
        float* sred = (float*)(smem + FU_STG);   // [mwarp][2][128]
        if (lane < 4) {
#pragma unroll
            for (int nf = 0; nf < 4; nf++)
#pragma unroll
                for (int j = 0; j < 2; j++) {
                    int col = wn0 + nf * 8 + lane * 2 + j;
                    sred[(mwarp * 2 + 0) * 128 + col] = cs[nf][j];
                    sred[(mwarp * 2 + 1) * 128 + col] = cq[nf][j];
                }
        }
        __syncthreads();
        if (tid < 128) {
            g_psum[blockIdx.y * HD + bn + tid] = sred[0 * 128 + tid] + sred[2 * 128 + tid];
            g_psq [blockIdx.y * HD + bn + tid] = sred[1 * 128 + tid] + sred[3 * 128 + tid];
        }
        __syncthreads();
    }

    // ---- loop 2: iv pre-activation ----
#pragma unroll
    for (int i = 0; i < 4; i++)
#pragma unroll
        for (int j = 0; j < 4; j++)
#pragma unroll
            for (int q = 0; q < 4; q++) acc[i][j][q] = 0.f;

    fused_mainloop(sb, A2 + (size_t)bm * HD, Wv + (size_t)bn * HD,
                   tid, lane, wm0, wn0, acc);

    // ---- epilogue 2: P, M2 scalars + S_iv / S_muiv column partials ----
    {
        float p = 0.f, m2 = 0.f;
        float ci[4][2], cm[4][2];
#pragma unroll
        for (int nf = 0; nf < 4; nf++) { ci[nf][0]=ci[nf][1]=cm[nf][0]=cm[nf][1]=0.f; }
#pragma unroll
        for (int mf = 0; mf < 4; mf++) {
#pragma unroll
            for (int nf = 0; nf < 4; nf++) {
                const int ml = wm0 + mf * 16 + g;
                const int m0 = bm + ml;
                const int n  = bn + wn0 + nf * 8 + tq * 2;
                const int nl = wn0 + nf * 8 + tq * 2;
                const float bv0 = __ldg(&bv_[n]);
                const float bv1 = __ldg(&bv_[n + 1]);
                float iv00 = __expf(-tanhf(acc[mf][nf][0] + bv0));
                float iv01 = __expf(-tanhf(acc[mf][nf][1] + bv1));
                float iv10 = __expf(-tanhf(acc[mf][nf][2] + bv0));
                float iv11 = __expf(-tanhf(acc[mf][nf][3] + bv1));
                __nv_bfloat162 q0 = *(__nv_bfloat162*)(smem + FU_MU + ml * FU_MUSTR + nl * 2);
                __nv_bfloat162 q1 = *(__nv_bfloat162*)(smem + FU_MU + (ml + 8) * FU_MUSTR + nl * 2);
                float mu00 = __bfloat162float(q0.x), mu01 = __bfloat162float(q0.y);
                float mu10 = __bfloat162float(q1.x), mu11 = __bfloat162float(q1.y);
                float2 mb0 = *(const float2*)&mbin[(size_t)m0 * HD + n];
                float2 mb1 = *(const float2*)&mbin[(size_t)(m0 + 8) * HD + n];
                float d;
                d = mu00 - mb0.x; p += d * d * iv00;
                d = mu01 - mb0.y; p += d * d * iv01;
                d = mu10 - mb1.x; p += d * d * iv10;
                d = mu11 - mb1.y; p += d * d * iv11;
                m2 += mu00*mu00*iv00 + mu01*mu01*iv01 + mu10*mu10*iv10 + mu11*mu11*iv11;
                ci[nf][0] += iv00 + iv10;          ci[nf][1] += iv01 + iv11;
                cm[nf][0] += mu00*iv00 + mu10*iv10; cm[nf][1] += mu01*iv01 + mu11*iv11;
            }
        }
#pragma unroll
        for (int msk = 4; msk <= 16; msk <<= 1)
#pragma unroll
            for (int nf = 0; nf < 4; nf++)
#pragma unroll
                for (int j = 0; j < 2; j++) {
                    ci[nf][j] += __shfl_xor_sync(0xffffffff, ci[nf][j], msk);
                    cm[nf][j] += __shfl_xor_sync(0xffffffff, cm[nf][j], msk);
                }
#pragma unroll
        for (int msk = 16; msk >= 1; msk >>= 1) {
            p  += __shfl_xor_sync(0xffffffff, p,  msk);
            m2 += __shfl_xor_sync(0xffffffff, m2, msk);
        }
        float* sred = (float*)(smem + FU_STG);   // [mwarp][2][128] + 16 scalars
        float* ssc  = sred + 512;
        if (lane < 4) {
#pragma unroll
            for (int nf = 0; nf < 4; nf++)
#pragma unroll
                for (int j = 0; j < 2; j++) {
                    int col = wn0 + nf * 8 + lane * 2 + j;
                    sred[(mwarp * 2 + 0) * 128 + col] = ci[nf][j];
                    sred[(mwarp * 2 + 1) * 128 + col] = cm[nf][j];
                }
        }
        if (lane == 0) { ssc[wid] = p; ssc[8 + wid] = m2; }
        __syncthreads();
        if (tid < 128) {
            g_siv  [blockIdx.y * HD + bn + tid] = sred[0 * 128 + tid] + sred[2 * 128 + tid];
            g_smuiv[blockIdx.y * HD + bn + tid] = sred[1 * 128 + tid] + sred[3 * 128 + tid];
        }
        if (tid == 0) {
            float P = 0.f, M2 = 0.f;
#pragma unroll
            for (int w = 0; w < 8; w++) { P += ssc[w]; M2 += ssc[8 + w]; }
            int bid = blockIdx.y * gridDim.x + blockIdx.x;
            g_ppos[bid] = P;
            g_pm2 [bid] = M2;
        }
    }
}

// ---------------------------------------------------------------------------
// fc1 (coalesced): warp = slab-group of 8, lane = column within 32-col block.
// grid 24 x 256.
__global__ void fc1()
{
    const int tid  = threadIdx.x;
    const int lane = tid & 31;
    const int w    = tid >> 5;            // 0..7
    const int h    = blockIdx.x * 32 + lane;

    float smu = 0.f, sm2 = 0.f, siv = 0.f, smv = 0.f;
#pragma unroll
    for (int s = 0; s < 8; s++) {
        int idx = (w * 8 + s) * HD + h;   // coalesced across lanes
        smu += g_psum[idx]; sm2 += g_psq[idx];
        siv += g_siv[idx];  smv += g_smuiv[idx];
    }
    __shared__ float red[4][8][32];
    red[0][w][lane] = smu; red[1][w][lane] = sm2;
    red[2][w][lane] = siv; red[3][w][lane] = smv;
    __syncthreads();
    if (w == 0) {
        float a = 0.f, b = 0.f, c = 0.f, d = 0.f;
#pragma unroll
        for (int k = 0; k < 8; k++) {
            a += red[0][k][lane]; b += red[1][k][lane];
            c += red[2][k][lane]; d += red[3][k][lane];
        }
        float neg = (b * (1.0f / MB_)) * c - 2.0f * (a * (1.0f / MB_)) * d;
#pragma unroll
        for (int msk = 16; msk >= 1; msk >>= 1)
            neg += __shfl_xor_sync(0xffffffff, neg, msk);
        if (lane == 0) g_negp[blockIdx.x] = neg;
    }
}

// fc2: final scalars
__global__ void fc2(float* __restrict__ out)
{
    const int tid = threadIdx.x;       // 128 threads
    float p = 0.f, m2 = 0.f, ng = 0.f;
    for (int i = tid; i < 384; i += 128) { p += g_ppos[i]; m2 += g_pm2[i]; }
    if (tid < 24) ng = g_negp[tid];
    __shared__ float sp[128], sm[128], sg_[128];
    sp[tid] = p; sm[tid] = m2; sg_[tid] = ng;
    __syncthreads();
    for (int s = 64; s > 0; s >>= 1) {
        if (tid < s) { sp[tid] += sp[tid+s]; sm[tid] += sm[tid+s]; sg_[tid] += sg_[tid+s]; }
        __syncthreads();
    }
    if (tid == 0) {
        float P = sp[0];
        float N = sg_[0] + sm[0];
        out[0] = -0.5f * P / (float)MB_;
        out[1] = 0.5f * (N - P) / (float)MB_;
    }
}

// ---------------------------------------------------------------------------
extern "C" void kernel_launch(void* const* d_in, const int* in_sizes, int n_in,
                              void* d_out, int out_size)
{
    const float* A   = (const float*)d_in[0];
    const float* Mb  = (const float*)d_in[1];
    const float* W1m = (const float*)d_in[2];
    const float* b1m = (const float*)d_in[3];
    const float* W2m = (const float*)d_in[4];
    const float* b2m = (const float*)d_in[5];
    const float* W1v = (const float*)d_in[6];
    const float* b1v = (const float*)d_in[7];
    const float* W2v = (const float*)d_in[8];
    const float* b2v = (const float*)d_in[9];

    __nv_bfloat16 *abf, *w1m, *w1v, *w2m, *w2v, *t1m, *t1v;
    cudaGetSymbolAddress((void**)&abf, g_abf);
    cudaGetSymbolAddress((void**)&w1m, g_w1m);
    cudaGetSymbolAddress((void**)&w1v, g_w1v);
    cudaGetSymbolAddress((void**)&w2m, g_w2m);
    cudaGetSymbolAddress((void**)&w2v, g_w2v);
    cudaGetSymbolAddress((void**)&t1m, g_t1m);
    cudaGetSymbolAddress((void**)&t1v, g_t1v);

    cudaFuncSetAttribute(gemm_tanh,    cudaFuncAttributeMaxDynamicSharedMemorySize, GT_SMEM);
    cudaFuncSetAttribute(gemm_fused34, cudaFuncAttributeMaxDynamicSharedMemorySize, FU_SMEM);

    cvt_all<<<6144 + 4 * 576, 256>>>(A, W1m, W1v, W2m, W2v);

    dim3 grid12(HD / 128, MB_ / 128, 2);  // (6, 64, 2)
    gemm_tanh<<<grid12, 256, GT_SMEM>>>(abf, w1m, w1v, b1m, b1v, t1m, t1v);

    dim3 grid(HD / 128, MB_ / 128);       // (6, 64)
    gemm_fused34<<<grid, 256, FU_SMEM>>>(t1m, w2m, b2m, t1v, w2v, b2v, Mb);

    fc1<<<24, 256>>>();
    fc2<<<1, 128>>>((float*)d_out);
}